// round 11
// baseline (speedup 1.0000x reference)
#include <cuda_runtime.h>
#include <cuda_fp16.h>
#include <cstdint>

// Problem constants (fixed by the dataset)
#define T_TOK 16384
#define DDIM  1024
#define NEXP  8

// GEMM tiling: CTA 128x128, warp 32x64 (8 warps: 4 rows x 2 cols)
#define MT  128
#define NT  128
#define KC  64
#define NCH (DDIM / KC)          // 16 k-chunks
#define NSTAGE 3
#define STAGE_B 32768            // A(16KB) + B(16KB) per stage
#define SMEM_DYN (NSTAGE * STAGE_B)  // 96KB -> 2 CTAs/SM
#define NPERS 296                // persistent CTAs = 148 SMs x 2

// ---------------------------------------------------------------------------
// Scratch (device globals; allocation is forbidden)
// ---------------------------------------------------------------------------
__device__ int    g_count[NEXP];
__device__ int    g_tok [NEXP][T_TOK];
__device__ float  g_gate[NEXP][T_TOK];
__device__ float  g_logits[(size_t)T_TOK * NEXP];
__device__ __half g_xf[(size_t)T_TOK * DDIM];             // x in fp16
__device__ __half g_wf[(size_t)NEXP * DDIM * DDIM];       // We in fp16

// ---------------------------------------------------------------------------
// PTX helpers (base-ISA only: plain sm_103 target)
// ---------------------------------------------------------------------------
__device__ __forceinline__ uint32_t smem_u32(const void* p) {
    uint32_t a;
    asm("{ .reg .u64 t; cvta.to.shared.u64 t, %1; cvt.u32.u64 %0, t; }" : "=r"(a) : "l"(p));
    return a;
}
__device__ __forceinline__ uint32_t swz(uint32_t o) { return o ^ ((o >> 3) & 0x70); }

__device__ __forceinline__ void cp16(uint32_t dst, const void* src) {
    asm volatile("cp.async.cg.shared.global [%0], [%1], 16;" :: "r"(dst), "l"(src));
}
#define CP_COMMIT() asm volatile("cp.async.commit_group;" ::: "memory")
#define CP_WAIT(n)  asm volatile("cp.async.wait_group %0;" :: "n"(n) : "memory")

__device__ __forceinline__ void ldmx4(uint32_t* r, uint32_t addr) {
    asm volatile("ldmatrix.sync.aligned.m8n8.x4.shared.b16 {%0,%1,%2,%3}, [%4];"
                 : "=r"(r[0]), "=r"(r[1]), "=r"(r[2]), "=r"(r[3]) : "r"(addr));
}

__device__ __forceinline__ void mma16816(float* c, const uint32_t* a, const uint32_t* b) {
    asm volatile("mma.sync.aligned.m16n8k16.row.col.f32.f16.f16.f32 "
                 "{%0,%1,%2,%3}, {%4,%5,%6,%7}, {%8,%9}, {%0,%1,%2,%3};"
                 : "+f"(c[0]), "+f"(c[1]), "+f"(c[2]), "+f"(c[3])
                 : "r"(a[0]), "r"(a[1]), "r"(a[2]), "r"(a[3]), "r"(b[0]), "r"(b[1]));
}

__device__ __forceinline__ void red_v2(float* p, float v0, float v1) {
    asm volatile("red.global.add.v2.f32 [%0], {%1, %2};" :: "l"(p), "f"(v0), "f"(v1) : "memory");
}

// ---------------------------------------------------------------------------
// Kernel 0: fused zero(out) + counter reset + We fp32->fp16 (one HBM pass)
// ---------------------------------------------------------------------------
__global__ void prep_kernel(float* __restrict__ out, const float* __restrict__ w) {
    const int b = blockIdx.x;
    const int tid = threadIdx.x;
    if (b < 16384) {
        int i = b * 256 + tid;
        reinterpret_cast<float4*>(out)[i] = make_float4(0.f, 0.f, 0.f, 0.f);
        if (b == 0 && tid < NEXP) g_count[tid] = 0;
    } else {
        int i = (b - 16384) * 256 + tid;
        float4 v = reinterpret_cast<const float4*>(w)[i];
        __half2* d = reinterpret_cast<__half2*>(g_wf);
        d[i * 2 + 0] = __floats2half2_rn(v.x, v.y);
        d[i * 2 + 1] = __floats2half2_rn(v.z, v.w);
    }
}

// ---------------------------------------------------------------------------
// Kernel 1: fused x fp32->fp16 convert + gate logits. One block = one token.
// ---------------------------------------------------------------------------
__global__ void __launch_bounds__(256)
cvt_x_gate_kernel(const float* __restrict__ x,
                  const float* __restrict__ Wg,
                  const float* __restrict__ bg) {
    const int t = blockIdx.x;
    const int i = threadIdx.x;

    float4 v = reinterpret_cast<const float4*>(x + (size_t)t * DDIM)[i];

    __half2* d = reinterpret_cast<__half2*>(g_xf + (size_t)t * DDIM);
    d[i * 2 + 0] = __floats2half2_rn(v.x, v.y);
    d[i * 2 + 1] = __floats2half2_rn(v.z, v.w);

    float acc[NEXP];
#pragma unroll
    for (int e = 0; e < NEXP; e++) {
        float4 w = reinterpret_cast<const float4*>(Wg + e * DDIM)[i];
        acc[e] = v.x * w.x + v.y * w.y + v.z * w.z + v.w * w.w;
    }
#pragma unroll
    for (int off = 16; off > 0; off >>= 1)
#pragma unroll
        for (int e = 0; e < NEXP; e++)
            acc[e] += __shfl_xor_sync(0xFFFFFFFFu, acc[e], off);

    __shared__ float red[8][NEXP];
    const int warp = i >> 5, lane = i & 31;
    if (lane == 0)
#pragma unroll
        for (int e = 0; e < NEXP; e++) red[warp][e] = acc[e];
    __syncthreads();

    if (i < NEXP) {
        float s = bg[i];
#pragma unroll
        for (int w = 0; w < 8; w++) s += red[w][i];
        g_logits[(size_t)t * NEXP + i] = s;
    }
}

// ---------------------------------------------------------------------------
// Kernel 2: top-2 + softmax + block-aggregated compaction.
// ---------------------------------------------------------------------------
__global__ void __launch_bounds__(256)
topk_kernel() {
    const int tid = threadIdx.x;
    const int t = blockIdx.x * 256 + tid;

    __shared__ int cnt_s[NEXP];
    __shared__ int base_s[NEXP];
    if (tid < NEXP) cnt_s[tid] = 0;
    __syncthreads();

    float l[NEXP];
    float4 l0 = reinterpret_cast<const float4*>(g_logits + (size_t)t * NEXP)[0];
    float4 l1 = reinterpret_cast<const float4*>(g_logits + (size_t)t * NEXP)[1];
    l[0]=l0.x; l[1]=l0.y; l[2]=l0.z; l[3]=l0.w;
    l[4]=l1.x; l[5]=l1.y; l[6]=l1.z; l[7]=l1.w;

    int i0 = 0;
#pragma unroll
    for (int e = 1; e < NEXP; e++) if (l[e] > l[i0]) i0 = e;
    int i1 = (i0 == 0) ? 1 : 0;
#pragma unroll
    for (int e = 0; e < NEXP; e++) {
        if (e == i0) continue;
        if (l[e] > l[i1]) i1 = e;
    }
    float m  = fmaxf(l[i0], l[i1]);
    float e0 = __expf(l[i0] - m);
    float e1 = __expf(l[i1] - m);
    float inv = 1.f / (e0 + e1);

    int p0 = atomicAdd(&cnt_s[i0], 1);
    int p1 = atomicAdd(&cnt_s[i1], 1);
    __syncthreads();
    if (tid < NEXP) base_s[tid] = atomicAdd(&g_count[tid], cnt_s[tid]);
    __syncthreads();

    int q0 = base_s[i0] + p0;
    g_tok[i0][q0] = t; g_gate[i0][q0] = e0 * inv;
    int q1 = base_s[i1] + p1;
    g_tok[i1][q1] = t; g_gate[i1][q1] = e1 * inv;
}

// ---------------------------------------------------------------------------
// Kernel 3: PERSISTENT fp16 HMMA expert GEMM. 296 CTAs, each loops over
// tiles with stride 296. CTA tile 128x128, warp 32x64, 3-stage cp.async
// ring carried across tile boundaries; next tile's token staging + 2-chunk
// prologue issued BEFORE the current tile's epilogue (bubble hidden).
// ---------------------------------------------------------------------------
__global__ void __launch_bounds__(256, 2)
moe_gemm_kernel(const float* __restrict__ be, float* __restrict__ out) {
    // total tile count
    int ty_tot = 0;
#pragma unroll
    for (int q = 0; q < NEXP; q++) ty_tot += (g_count[q] + MT - 1) / MT;
    const int ntiles = ty_tot * 8;

    int tile = blockIdx.x;
    if (tile >= ntiles) return;

    extern __shared__ __align__(128) char smem[];
    const uint32_t sbase = smem_u32(smem);

    __shared__ int   s_tok[2][MT];
    __shared__ float s_gate[2][MT];

    const int tid  = threadIdx.x;
    const int wid  = tid >> 5, lane = tid & 31;
    const int wm   = (wid & 3) * 32;     // warp row offset in tile
    const int wn   = (wid >> 2) * 64;    // warp col offset in tile

    // tile -> (expert, m0, n0)
    auto decode = [&](int t, int& e, int& m0, int& n0) {
        int y = t >> 3; n0 = (t & 7) * NT;
        int s = 0; e = -1; m0 = 0;
#pragma unroll
        for (int q = 0; q < NEXP; q++) {
            int nt = (g_count[q] + MT - 1) / MT;
            if (e < 0 && y < s + nt) { e = q; m0 = (y - s) * MT; }
            s += nt;
        }
    };

    // stage loader: A rows gathered via s_tok[buf], B rows from g_wf
    auto load_stage = [&](size_t wbase, int buf, int ck, int slot) {
        const int k0 = ck * KC;
        const uint32_t sA = sbase + slot * STAGE_B;
        const uint32_t sB = sA + 16384;
#pragma unroll
        for (int i = 0; i < 4; i++) {
            int u = tid + i * 256;               // 0..1023
            int row = u >> 3, c = u & 7;         // 128 rows x 8 16B-chunks
            const __half* src = &g_xf[(size_t)s_tok[buf][row] * DDIM + k0 + c * 8];
            cp16(sA + swz((uint32_t)(row * 128 + c * 16)), src);
        }
#pragma unroll
        for (int i = 0; i < 4; i++) {
            int u = tid + i * 256;
            int row = u >> 3, c = u & 7;
            const __half* src = &g_wf[wbase + (size_t)row * DDIM + k0 + c * 8];
            cp16(sB + swz((uint32_t)(row * 128 + c * 16)), src);
        }
        CP_COMMIT();
    };

    // ---- first tile setup ----
    int e, m0, n0;
    decode(tile, e, m0, n0);
    int cnt = g_count[e];
    int buf = 0;
    if (tid < MT) {
        int m = m0 + tid;
        s_tok[0][tid]  = (m < cnt) ? g_tok[e][m]  : 0;
        s_gate[0][tid] = (m < cnt) ? g_gate[e][m] : 0.f;
    }
    __syncthreads();
    size_t wbase = ((size_t)e << 20) + (size_t)n0 * DDIM;
    int so = 0;                          // ring phase for this tile's chunk 0
    load_stage(wbase, 0, 0, 0);
    load_stage(wbase, 0, 1, 1);

    float acc[2][8][4];
#pragma unroll
    for (int mi = 0; mi < 2; mi++)
#pragma unroll
        for (int ni = 0; ni < 8; ni++)
#pragma unroll
            for (int q = 0; q < 4; q++) acc[mi][ni][q] = 0.f;

    // ---- persistent tile loop ----
    for (;;) {
        // mainloop: 16 k-chunks
        int sl = so;
#pragma unroll 1
        for (int ck = 0; ck < NCH; ck++) {
            if (ck + 1 < NCH) { CP_WAIT(1); } else { CP_WAIT(0); }
            __syncthreads();
            if (ck + 2 < NCH) {
                int ps = sl + 2; if (ps >= 3) ps -= 3;
                load_stage(wbase, buf, ck + 2, ps);
            }

            const uint32_t sA = sbase + sl * STAGE_B;
            const uint32_t sB = sA + 16384;

#pragma unroll
            for (int ks = 0; ks < 4; ks++) {
                uint32_t a[2][4];
#pragma unroll
                for (int mi = 0; mi < 2; mi++) {
                    int row = wm + mi * 16 + (lane & 15);
                    ldmx4(a[mi], sA + swz((uint32_t)(row * 128 + (ks * 2 + (lane >> 4)) * 16)));
                }
                uint32_t b[4][4];
#pragma unroll
                for (int pi = 0; pi < 4; pi++) {
                    int n = wn + pi * 16 + ((lane >> 4) << 3) + (lane & 7);
                    ldmx4(b[pi], sB + swz((uint32_t)(n * 128 + (ks * 2 + ((lane >> 3) & 1)) * 16)));
                }
#pragma unroll
                for (int mi = 0; mi < 2; mi++)
#pragma unroll
                    for (int ni = 0; ni < 8; ni++)
                        mma16816(acc[mi][ni], a[mi], &b[ni >> 1][(ni & 1) * 2]);
            }
            sl++; if (sl >= 3) sl -= 3;
        }

        // save current tile params for the epilogue
        const int pe = e, pm0 = m0, pn0 = n0, pcnt = cnt, pbuf = buf;

        // next tile: stage token list + 2-chunk prologue BEFORE epilogue
        tile += NPERS;
        const bool nx = (tile < ntiles);
        int nso = so + 1; if (nso >= 3) nso -= 3;   // (so+16)%3
        if (nx) {
            decode(tile, e, m0, n0);
            cnt = g_count[e];
            buf ^= 1;
            if (tid < MT) {
                int m = m0 + tid;
                s_tok[buf][tid]  = (m < cnt) ? g_tok[e][m]  : 0;
                s_gate[buf][tid] = (m < cnt) ? g_gate[e][m] : 0.f;
            }
            __syncthreads();
            wbase = ((size_t)e << 20) + (size_t)n0 * DDIM;
            int s1 = nso + 1; if (s1 >= 3) s1 -= 3;
            load_stage(wbase, buf, 0, nso);
            load_stage(wbase, buf, 1, s1);
        }

        // ---- epilogue for the saved tile (overlaps the cp.async refill) ----
        {
            const float* brow = be + (size_t)pe * DDIM + pn0 + wn;
            float2 bias[8];
#pragma unroll
            for (int ni = 0; ni < 8; ni++)
                bias[ni] = *reinterpret_cast<const float2*>(brow + ni * 8 + 2 * (lane & 3));

#pragma unroll
            for (int mi = 0; mi < 2; mi++)
#pragma unroll
                for (int h = 0; h < 2; h++) {
                    int mrow = wm + mi * 16 + (lane >> 2) + h * 8;
                    if (pm0 + mrow < pcnt) {
                        int tok = s_tok[pbuf][mrow];
                        float g = s_gate[pbuf][mrow];
                        float* orow = out + (size_t)tok * DDIM + pn0 + wn + 2 * (lane & 3);
#pragma unroll
                        for (int ni = 0; ni < 8; ni++) {
                            red_v2(orow + ni * 8,
                                   g * (acc[mi][ni][h * 2 + 0] + bias[ni].x),
                                   g * (acc[mi][ni][h * 2 + 1] + bias[ni].y));
                        }
                    }
                }
        }

        if (!nx) return;

        // reset accumulators for the next tile
#pragma unroll
        for (int mi = 0; mi < 2; mi++)
#pragma unroll
            for (int ni = 0; ni < 8; ni++)
#pragma unroll
                for (int q = 0; q < 4; q++) acc[mi][ni][q] = 0.f;
        so = nso;
    }
}

// ---------------------------------------------------------------------------
extern "C" void kernel_launch(void* const* d_in, const int* in_sizes, int n_in,
                              void* d_out, int out_size) {
    const float* x  = (const float*)d_in[0];   // [16384, 1024]
    const float* Wg = (const float*)d_in[1];   // [8, 1024]
    const float* bg = (const float*)d_in[2];   // [8]
    const float* We = (const float*)d_in[3];   // [8, 1024, 1024]
    const float* be = (const float*)d_in[4];   // [8, 1024]
    float* out = (float*)d_out;                // [16384, 1024]

    cudaFuncSetAttribute(moe_gemm_kernel,
                         cudaFuncAttributeMaxDynamicSharedMemorySize, SMEM_DYN);

    prep_kernel<<<16384 + 8192, 256>>>(out, We);
    cvt_x_gate_kernel<<<T_TOK, 256>>>(x, Wg, bg);
    topk_kernel<<<T_TOK / 256, 256>>>();

    moe_gemm_kernel<<<NPERS, 256, SMEM_DYN>>>(be, out);
}

// round 12
// speedup vs baseline: 1.1076x; 1.1076x over previous
#include <cuda_runtime.h>
#include <cuda_fp16.h>
#include <cstdint>

// Problem constants (fixed by the dataset)
#define T_TOK 16384
#define DDIM  1024
#define NEXP  8

// GEMM tiling: CTA 128x128, warp 32x64 (8 warps: 4 rows x 2 cols)
#define MT  128
#define NT  128
#define KC  64
#define NCH (DDIM / KC)          // 16 k-chunks
#define NSTAGE 3
#define STAGE_B 32768            // A(16KB) + B(16KB) per stage
#define SMEM_DYN (NSTAGE * STAGE_B)  // 96KB -> 2 CTAs/SM
#define MAX_TILES 136            // per rank: sum ceil(cnt_e/128) <= 128 + 8

// ---------------------------------------------------------------------------
// Scratch (device globals; allocation is forbidden)
// ---------------------------------------------------------------------------
__device__ int    g_cnt2 [2][NEXP];
__device__ int    g_tok2 [2][NEXP][T_TOK];
__device__ float  g_gate2[2][NEXP][T_TOK];
__device__ float  g_logits[(size_t)T_TOK * NEXP];
__device__ __half g_xf[(size_t)T_TOK * DDIM];             // x in fp16
__device__ __half g_wf[(size_t)NEXP * DDIM * DDIM];       // We in fp16

// ---------------------------------------------------------------------------
// PTX helpers (base-ISA only: plain sm_103 target)
// ---------------------------------------------------------------------------
__device__ __forceinline__ uint32_t smem_u32(const void* p) {
    uint32_t a;
    asm("{ .reg .u64 t; cvta.to.shared.u64 t, %1; cvt.u32.u64 %0, t; }" : "=r"(a) : "l"(p));
    return a;
}
__device__ __forceinline__ uint32_t swz(uint32_t o) { return o ^ ((o >> 3) & 0x70); }

__device__ __forceinline__ void cp16(uint32_t dst, const void* src) {
    asm volatile("cp.async.cg.shared.global [%0], [%1], 16;" :: "r"(dst), "l"(src));
}
#define CP_COMMIT() asm volatile("cp.async.commit_group;" ::: "memory")
#define CP_WAIT(n)  asm volatile("cp.async.wait_group %0;" :: "n"(n) : "memory")

__device__ __forceinline__ void ldmx4(uint32_t* r, uint32_t addr) {
    asm volatile("ldmatrix.sync.aligned.m8n8.x4.shared.b16 {%0,%1,%2,%3}, [%4];"
                 : "=r"(r[0]), "=r"(r[1]), "=r"(r[2]), "=r"(r[3]) : "r"(addr));
}

__device__ __forceinline__ void mma16816(float* c, const uint32_t* a, const uint32_t* b) {
    asm volatile("mma.sync.aligned.m16n8k16.row.col.f32.f16.f16.f32 "
                 "{%0,%1,%2,%3}, {%4,%5,%6,%7}, {%8,%9}, {%0,%1,%2,%3};"
                 : "+f"(c[0]), "+f"(c[1]), "+f"(c[2]), "+f"(c[3])
                 : "r"(a[0]), "r"(a[1]), "r"(a[2]), "r"(a[3]), "r"(b[0]), "r"(b[1]));
}

__device__ __forceinline__ void red_v2(float* p, float v0, float v1) {
    asm volatile("red.global.add.v2.f32 [%0], {%1, %2};" :: "l"(p), "f"(v0), "f"(v1) : "memory");
}

// ---------------------------------------------------------------------------
// Kernel 0: counter reset + We fp32->fp16 (no output zeroing needed anymore)
// ---------------------------------------------------------------------------
__global__ void prep_kernel(const float* __restrict__ w) {
    const int b = blockIdx.x;
    const int tid = threadIdx.x;
    if (b == 0 && tid < 2 * NEXP) ((int*)g_cnt2)[tid] = 0;
    int i = b * 256 + tid;
    float4 v = reinterpret_cast<const float4*>(w)[i];
    __half2* d = reinterpret_cast<__half2*>(g_wf);
    d[i * 2 + 0] = __floats2half2_rn(v.x, v.y);
    d[i * 2 + 1] = __floats2half2_rn(v.z, v.w);
}

// ---------------------------------------------------------------------------
// Kernel 1: fused x fp32->fp16 convert + gate logits. One block = one token.
// ---------------------------------------------------------------------------
__global__ void __launch_bounds__(256)
cvt_x_gate_kernel(const float* __restrict__ x,
                  const float* __restrict__ Wg,
                  const float* __restrict__ bg) {
    const int t = blockIdx.x;
    const int i = threadIdx.x;

    float4 v = reinterpret_cast<const float4*>(x + (size_t)t * DDIM)[i];

    __half2* d = reinterpret_cast<__half2*>(g_xf + (size_t)t * DDIM);
    d[i * 2 + 0] = __floats2half2_rn(v.x, v.y);
    d[i * 2 + 1] = __floats2half2_rn(v.z, v.w);

    float acc[NEXP];
#pragma unroll
    for (int e = 0; e < NEXP; e++) {
        float4 w = reinterpret_cast<const float4*>(Wg + e * DDIM)[i];
        acc[e] = v.x * w.x + v.y * w.y + v.z * w.z + v.w * w.w;
    }
#pragma unroll
    for (int off = 16; off > 0; off >>= 1)
#pragma unroll
        for (int e = 0; e < NEXP; e++)
            acc[e] += __shfl_xor_sync(0xFFFFFFFFu, acc[e], off);

    __shared__ float red[8][NEXP];
    const int warp = i >> 5, lane = i & 31;
    if (lane == 0)
#pragma unroll
        for (int e = 0; e < NEXP; e++) red[warp][e] = acc[e];
    __syncthreads();

    if (i < NEXP) {
        float s = bg[i];
#pragma unroll
        for (int w = 0; w < 8; w++) s += red[w][i];
        g_logits[(size_t)t * NEXP + i] = s;
    }
}

// ---------------------------------------------------------------------------
// Kernel 2: top-2 + softmax + rank-split block-aggregated compaction.
// rank0 = top-1 expert per token, rank1 = second expert.
// ---------------------------------------------------------------------------
__global__ void __launch_bounds__(256)
topk_kernel() {
    const int tid = threadIdx.x;
    const int t = blockIdx.x * 256 + tid;

    __shared__ int cnt_s[2][NEXP];
    __shared__ int base_s[2][NEXP];
    if (tid < 2 * NEXP) ((int*)cnt_s)[tid] = 0;
    __syncthreads();

    float l[NEXP];
    float4 l0 = reinterpret_cast<const float4*>(g_logits + (size_t)t * NEXP)[0];
    float4 l1 = reinterpret_cast<const float4*>(g_logits + (size_t)t * NEXP)[1];
    l[0]=l0.x; l[1]=l0.y; l[2]=l0.z; l[3]=l0.w;
    l[4]=l1.x; l[5]=l1.y; l[6]=l1.z; l[7]=l1.w;

    int i0 = 0;
#pragma unroll
    for (int e = 1; e < NEXP; e++) if (l[e] > l[i0]) i0 = e;
    int i1 = (i0 == 0) ? 1 : 0;
#pragma unroll
    for (int e = 0; e < NEXP; e++) {
        if (e == i0) continue;
        if (l[e] > l[i1]) i1 = e;
    }
    float m  = fmaxf(l[i0], l[i1]);
    float e0 = __expf(l[i0] - m);
    float e1 = __expf(l[i1] - m);
    float inv = 1.f / (e0 + e1);

    int p0 = atomicAdd(&cnt_s[0][i0], 1);
    int p1 = atomicAdd(&cnt_s[1][i1], 1);
    __syncthreads();
    if (tid < 2 * NEXP) {
        int r = tid >> 3, e = tid & 7;
        base_s[r][e] = atomicAdd(&g_cnt2[r][e], cnt_s[r][e]);
    }
    __syncthreads();

    int q0 = base_s[0][i0] + p0;
    g_tok2[0][i0][q0] = t; g_gate2[0][i0][q0] = e0 * inv;
    int q1 = base_s[1][i1] + p1;
    g_tok2[1][i1][q1] = t; g_gate2[1][i1][q1] = e1 * inv;
}

// ---------------------------------------------------------------------------
// Kernel 3: fp16 HMMA expert GEMM, CTA 128x128, warp 32x64, 3-stage cp.async,
// 2 CTAs/SM. Templated on rank list and epilogue mode:
//   RANK=0, STORE=true : plain STG (covers every output elem exactly once)
//   RANK=1, STORE=false: red.global.add (second expert contribution)
// ---------------------------------------------------------------------------
template <int RANK, bool STORE>
__global__ void __launch_bounds__(256, 2)
moe_gemm_kernel(const float* __restrict__ be, float* __restrict__ out) {
    int e = -1, m0 = 0;
    {
        int ty = blockIdx.y, s = 0;
#pragma unroll
        for (int q = 0; q < NEXP; q++) {
            int nt = (g_cnt2[RANK][q] + MT - 1) / MT;
            if (e < 0 && ty < s + nt) { e = q; m0 = (ty - s) * MT; }
            s += nt;
        }
    }
    if (e < 0) return;
    const int cnt = g_cnt2[RANK][e];
    const int n0  = blockIdx.x * NT;

    extern __shared__ __align__(128) char smem[];
    const uint32_t sbase = smem_u32(smem);

    __shared__ int   s_tok[MT];
    __shared__ float s_gate[MT];

    const int tid  = threadIdx.x;
    const int wid  = tid >> 5, lane = tid & 31;
    const int wm   = (wid & 3) * 32;     // warp row offset in tile
    const int wn   = (wid >> 2) * 64;    // warp col offset in tile

    if (tid < MT) {
        int m = m0 + tid;
        s_tok[tid]  = (m < cnt) ? g_tok2[RANK][e][m]  : 0;
        s_gate[tid] = (m < cnt) ? g_gate2[RANK][e][m] : 0.f;
    }
    __syncthreads();

    const size_t wbase = ((size_t)e << 20) + (size_t)n0 * DDIM;  // e*1024*1024

    auto load_stage = [&](int ck, int s) {
        const int k0 = ck * KC;
        const uint32_t sA = sbase + s * STAGE_B;
        const uint32_t sB = sA + 16384;
#pragma unroll
        for (int i = 0; i < 4; i++) {
            int u = tid + i * 256;               // 0..1023
            int row = u >> 3, c = u & 7;         // 128 rows x 8 16B-chunks
            const __half* src = &g_xf[(size_t)s_tok[row] * DDIM + k0 + c * 8];
            cp16(sA + swz((uint32_t)(row * 128 + c * 16)), src);
        }
#pragma unroll
        for (int i = 0; i < 4; i++) {
            int u = tid + i * 256;
            int row = u >> 3, c = u & 7;
            const __half* src = &g_wf[wbase + (size_t)row * DDIM + k0 + c * 8];
            cp16(sB + swz((uint32_t)(row * 128 + c * 16)), src);
        }
        CP_COMMIT();
    };

    float acc[2][8][4];
#pragma unroll
    for (int mi = 0; mi < 2; mi++)
#pragma unroll
        for (int ni = 0; ni < 8; ni++)
#pragma unroll
            for (int q = 0; q < 4; q++) acc[mi][ni][q] = 0.f;

    load_stage(0, 0);
    load_stage(1, 1);

#pragma unroll 1
    for (int ck = 0; ck < NCH; ck++) {
        if (ck + 1 < NCH) { CP_WAIT(1); } else { CP_WAIT(0); }
        __syncthreads();
        // Slot (ck+2)%3 finished its MMAs at iteration ck-1 (barrier above).
        if (ck + 2 < NCH) load_stage(ck + 2, (ck + 2) % NSTAGE);

        const uint32_t sA = sbase + (ck % NSTAGE) * STAGE_B;
        const uint32_t sB = sA + 16384;

#pragma unroll
        for (int ks = 0; ks < 4; ks++) {
            uint32_t a[2][4];
#pragma unroll
            for (int mi = 0; mi < 2; mi++) {
                int row = wm + mi * 16 + (lane & 15);
                ldmx4(a[mi], sA + swz((uint32_t)(row * 128 + (ks * 2 + (lane >> 4)) * 16)));
            }
            uint32_t b[4][4];
#pragma unroll
            for (int pi = 0; pi < 4; pi++) {
                int n = wn + pi * 16 + ((lane >> 4) << 3) + (lane & 7);
                ldmx4(b[pi], sB + swz((uint32_t)(n * 128 + (ks * 2 + ((lane >> 3) & 1)) * 16)));
            }
#pragma unroll
            for (int mi = 0; mi < 2; mi++)
#pragma unroll
                for (int ni = 0; ni < 8; ni++)
                    mma16816(acc[mi][ni], a[mi], &b[ni >> 1][(ni & 1) * 2]);
        }
    }

    // --- epilogue ---
    const float* brow = be + (size_t)e * DDIM + n0 + wn;
    float2 bias[8];
#pragma unroll
    for (int ni = 0; ni < 8; ni++)
        bias[ni] = *reinterpret_cast<const float2*>(brow + ni * 8 + 2 * (lane & 3));

#pragma unroll
    for (int mi = 0; mi < 2; mi++)
#pragma unroll
        for (int h = 0; h < 2; h++) {
            int mrow = wm + mi * 16 + (lane >> 2) + h * 8;
            if (m0 + mrow < cnt) {
                int tok = s_tok[mrow];
                float g = s_gate[mrow];
                float* orow = out + (size_t)tok * DDIM + n0 + wn + 2 * (lane & 3);
#pragma unroll
                for (int ni = 0; ni < 8; ni++) {
                    float v0 = g * (acc[mi][ni][h * 2 + 0] + bias[ni].x);
                    float v1 = g * (acc[mi][ni][h * 2 + 1] + bias[ni].y);
                    if (STORE) {
                        *reinterpret_cast<float2*>(orow + ni * 8) = make_float2(v0, v1);
                    } else {
                        red_v2(orow + ni * 8, v0, v1);
                    }
                }
            }
        }
}

// ---------------------------------------------------------------------------
extern "C" void kernel_launch(void* const* d_in, const int* in_sizes, int n_in,
                              void* d_out, int out_size) {
    const float* x  = (const float*)d_in[0];   // [16384, 1024]
    const float* Wg = (const float*)d_in[1];   // [8, 1024]
    const float* bg = (const float*)d_in[2];   // [8]
    const float* We = (const float*)d_in[3];   // [8, 1024, 1024]
    const float* be = (const float*)d_in[4];   // [8, 1024]
    float* out = (float*)d_out;                // [16384, 1024]

    cudaFuncSetAttribute(moe_gemm_kernel<0, true>,
                         cudaFuncAttributeMaxDynamicSharedMemorySize, SMEM_DYN);
    cudaFuncSetAttribute(moe_gemm_kernel<1, false>,
                         cudaFuncAttributeMaxDynamicSharedMemorySize, SMEM_DYN);

    prep_kernel<<<NEXP * DDIM * DDIM / 4 / 256, 256>>>(We);
    cvt_x_gate_kernel<<<T_TOK, 256>>>(x, Wg, bg);
    topk_kernel<<<T_TOK / 256, 256>>>();

    dim3 grid(DDIM / NT, MAX_TILES);   // (8, 136) per rank
    moe_gemm_kernel<0, true ><<<grid, 256, SMEM_DYN>>>(be, out);  // ST pass
    moe_gemm_kernel<1, false><<<grid, 256, SMEM_DYN>>>(be, out);  // red pass
}